// round 8
// baseline (speedup 1.0000x reference)
#include <cuda_runtime.h>
#include <cuda_fp16.h>
#include <cstdint>
#include <cstddef>

#define DEVI static __device__ __forceinline__

namespace li {

constexpr int B = 32, T = 1024, IN = 1024, OUT = 1024;
constexpr int TT = 128;                 // time rows per tile (GEMM M)
constexpr int TO = 128;                 // out cols per CTA   (GEMM N)
constexpr int BK = 64;                  // K elements per slab
constexpr int SLABS = IN / BK;          // 16
constexpr int TILES = T / TT;           // 8
constexpr int G = TILES * SLABS;        // 128 slabs per CTA

constexpr int W_STAGE = TT * 128;       // W fp16 slab: 128 rows x 128B = 16KB
constexpr int XROW = 272;               // fp32 row: 256B data + 16B pad (bank spread)
constexpr int X_STAGE = TT * XROW;      // 34816
constexpr int XOFF = 2 * W_STAGE;       // 32768
constexpr int STAGING_OFF = XOFF + X_STAGE;  // 67584 = X stage-1 (aliased)
constexpr int STG_STRIDE = 136;         // halves; conflict-free epilogue/scan
constexpr int SMEM_DYN = XOFF + 2 * X_STAGE;  // 102400

__device__ __align__(16) __half g_Wh[(size_t)OUT * IN];  // 2MB W scratch only
__device__ int g_warr;  // W flag: 256 arrive + 256 consume, self-reset

DEVI uint32_t s2u(const void* p) {
  uint32_t a;
  asm("{ .reg .u64 t; cvta.to.shared.u64 t, %1; cvt.u32.u64 %0, t; }"
      : "=r"(a) : "l"(p));
  return a;
}
DEVI void cp16(uint32_t s, const void* g) {
  asm volatile("cp.async.cg.shared.global [%0], [%1], 16;" :: "r"(s), "l"(g)
               : "memory");
}
DEVI void cp_commit() { asm volatile("cp.async.commit_group;" ::: "memory"); }
DEVI void cp_wait0() { asm volatile("cp.async.wait_group 0;" ::: "memory"); }

DEVI void ldsm4(uint32_t* r, uint32_t a) {
  asm volatile("ldmatrix.sync.aligned.m8n8.x4.shared.b16 {%0,%1,%2,%3}, [%4];"
               : "=r"(r[0]), "=r"(r[1]), "=r"(r[2]), "=r"(r[3]) : "r"(a));
}
DEVI void lds64(float2& v, uint32_t a) {
  asm volatile("ld.shared.v2.f32 {%0,%1}, [%2];"
               : "=f"(v.x), "=f"(v.y) : "r"(a));
}
DEVI void mma16(float* c, const uint32_t* a, const uint32_t* b) {
  asm volatile(
      "mma.sync.aligned.m16n8k16.row.col.f32.f16.f16.f32 "
      "{%0,%1,%2,%3}, {%4,%5,%6,%7}, {%8,%9}, {%0,%1,%2,%3};"
      : "+f"(c[0]), "+f"(c[1]), "+f"(c[2]), "+f"(c[3])
      : "r"(a[0]), "r"(a[1]), "r"(a[2]), "r"(a[3]), "r"(b[0]), "r"(b[1]));
}
DEVI uint32_t packh2(float lo, float hi) {  // low half <- lo
  uint32_t d;
  asm("cvt.rn.f16x2.f32 %0, %1, %2;" : "=r"(d) : "f"(hi), "f"(lo));
  return d;
}
DEVI int ld_acq(const int* p) {
  int v;
  asm volatile("ld.acquire.gpu.global.b32 %0, [%1];" : "=r"(v) : "l"(p));
  return v;
}
DEVI int atom_add_rel(int* p, int v) {
  int o;
  asm volatile("atom.release.gpu.global.add.s32 %0, [%1], %2;"
               : "=r"(o) : "l"(p), "r"(v) : "memory");
  return o;
}
DEVI uint2 cvt2(float4 v) {
  __half2 a = __float22half2_rn({v.x, v.y});
  __half2 b = __float22half2_rn({v.z, v.w});
  uint2 u;
  u.x = *reinterpret_cast<unsigned*>(&a);
  u.y = *reinterpret_cast<unsigned*>(&b);
  return u;
}
DEVI void wait_consume(int* f, int thresh, int tid) {
  if (tid == 0) {
    while (ld_acq(f) < thresh) __nanosleep(128);
    const int old = atomicAdd(f, 1);
    if (old == 2 * thresh - 1) atomicExch(f, 0);
  }
  __syncthreads();
}

// ---- single fused kernel: W-cvt prologue + GEMM (fp32 X on the fly) + scan --
// 128 threads, 4 warps 2x2, warp tile 64x64, 2 CTAs/SM, one wave.
__global__ void __launch_bounds__(128, 2)
li_kernel(const float* __restrict__ X, const float4* __restrict__ Wf,
          const float* __restrict__ bias, const float* __restrict__ decay,
          float* __restrict__ out) {
  extern __shared__ __align__(16) char dsm[];
  const uint32_t sbase = s2u(dsm);

  const int tid = threadIdx.x;
  const int wid = tid >> 5;
  const int lane = tid & 31;
  const int bb = blockIdx.x >> 3;
  const int o0 = (blockIdx.x & 7) * TO;

  // ---- scan state: each thread owns one o-channel ----
  const float dcy = decay[o0 + tid];
  const float omd = 1.0f - dcy;
  const float bo = bias[o0 + tid];
  float u = 0.f;

  // ---- prologue: convert this CTA's 1/256 share of W into g_Wh scratch ----
  {
    uint2* wo = reinterpret_cast<uint2*>(g_Wh);
    const int wbase = blockIdx.x * 1024;
#pragma unroll
    for (int c = 0; c < 8; ++c) {
      const int j = wbase + c * 128 + tid;
      wo[j] = cvt2(Wf[j]);
    }
    __threadfence();
    __syncthreads();
    if (tid == 0) atom_add_rel(&g_warr, 1);
    wait_consume(&g_warr, 256, tid);
  }

  // ---- producer constants ----
  const int lr = tid >> 3;  // W: row 0..15 (+16*i)
  const int lc = tid & 7;
  const uint32_t w_sw = (uint32_t)lr * 128 + (uint32_t)((lc ^ (lr & 7)) << 4);
  const __half* Wg = g_Wh + (size_t)(o0 + lr) * IN + lc * 8;
  const float* Xg0 = X + ((size_t)bb * T + tid) * IN;  // thread's X row base

  // ---- mma constants ----
  const int warp_m = wid >> 1, warp_n = wid & 1;
  const int r = lane & 7;
  const int khB = (lane >> 3) & 1;
  // A (X, fp32 manual): row/k offsets within an X stage
  const uint32_t aR0 =
      (uint32_t)(warp_m * 64 + (lane >> 2)) * XROW + (uint32_t)(8 * (lane & 3));
  // B (W, ldmatrix): same mapping as before, W region now at offset 0
  const uint32_t bBase =
      (uint32_t)(warp_n * 64 + ((lane >> 4) << 3) + r) * 128;

  float acc[4][8][4];

  auto load_slab = [&](int g) {
    const int t0 = (g >> 4) * TT;
    const int k0 = (g & 15) * BK;
    // X fp32: thread owns row `tid`; 16 x 16B chunks into padded 272B rows
    const uint32_t xb = sbase + XOFF + (uint32_t)(g & 1) * X_STAGE;
    const float* Xs = Xg0 + (size_t)t0 * IN + k0;
#pragma unroll
    for (int c = 0; c < 16; ++c)
      cp16(xb + (uint32_t)tid * XROW + (uint32_t)c * 16, Xs + c * 4);
    // W fp16: 8 x 16B chunks, swizzled 128B rows
    const uint32_t wb = sbase + (uint32_t)(g & 1) * W_STAGE;
    const __half* Ws = Wg + k0;
#pragma unroll
    for (int i = 0; i < 8; ++i)
      cp16(wb + w_sw + (uint32_t)i * 2048, Ws + (size_t)i * 16 * IN);
  };

  int g = 0;
  load_slab(0);
  cp_commit();

  for (int tile = 0; tile < TILES; ++tile) {
#pragma unroll
    for (int mf = 0; mf < 4; ++mf)
#pragma unroll
      for (int nf = 0; nf < 8; ++nf)
#pragma unroll
        for (int j = 0; j < 4; ++j) acc[mf][nf][j] = 0.f;

    for (int ks = 0; ks < SLABS; ++ks) {
      cp_wait0();
      __syncthreads();
      if (g + 1 < G) {
        load_slab(g + 1);
        cp_commit();
      }
      const uint32_t xb = sbase + XOFF + (uint32_t)(g & 1) * X_STAGE;
      const uint32_t wb = sbase + (uint32_t)(g & 1) * W_STAGE;
#pragma unroll
      for (int kc = 0; kc < 4; ++kc) {
        // ---- A fragments: fp32 LDS + cvt (replaces ldmatrix) ----
        uint32_t A[4][4];
        const uint32_t ak = xb + aR0 + (uint32_t)kc * 64;
#pragma unroll
        for (int mf = 0; mf < 4; ++mf) {
          const uint32_t a0 = ak + (uint32_t)mf * (16 * XROW);
          float2 v00, v10, v01, v11;
          lds64(v00, a0);
          lds64(v10, a0 + 8 * XROW);
          lds64(v01, a0 + 32);
          lds64(v11, a0 + 8 * XROW + 32);
          A[mf][0] = packh2(v00.x, v00.y);
          A[mf][1] = packh2(v10.x, v10.y);
          A[mf][2] = packh2(v01.x, v01.y);
          A[mf][3] = packh2(v11.x, v11.y);
        }
        // ---- B fragments: W via ldmatrix (fp16, swizzled) ----
        uint32_t Bf[4][4];
        const uint32_t swB = (uint32_t)(((2 * kc + khB) ^ r) << 4);
#pragma unroll
        for (int p = 0; p < 4; ++p)
          ldsm4(Bf[p], wb + bBase + (uint32_t)p * 2048 + swB);
#pragma unroll
        for (int mf = 0; mf < 4; ++mf)
#pragma unroll
          for (int nf = 0; nf < 8; ++nf)
            mma16(acc[mf][nf], A[mf], &Bf[nf >> 1][(nf & 1) * 2]);
      }
      ++g;
    }

    // ---- epilogue: fragments -> fp16 staging (aliases X stage 1, which is
    // always the free buffer at tile boundaries: next prefetch targets 0) ----
    __syncthreads();  // all LDS reads of X stage 1 complete before overwrite
    unsigned* stg_u = reinterpret_cast<unsigned*>(dsm + STAGING_OFF);
#pragma unroll
    for (int mf = 0; mf < 4; ++mf)
#pragma unroll
      for (int nf = 0; nf < 8; ++nf) {
        const int row = warp_m * 64 + mf * 16 + (lane >> 2);
        const int col = warp_n * 64 + nf * 8 + 2 * (lane & 3);
        stg_u[(row * STG_STRIDE + col) >> 1] =
            packh2(acc[mf][nf][0], acc[mf][nf][1]);
        stg_u[((row + 8) * STG_STRIDE + col) >> 1] =
            packh2(acc[mf][nf][2], acc[mf][nf][3]);
      }
    __syncthreads();

    // ---- fused leaky-integrator scan; carry u persists across tiles ----
    {
      const __half* sh = reinterpret_cast<const __half*>(dsm + STAGING_OFF);
      float* ob = out + ((size_t)bb * T + tile * TT) * OUT + o0 + tid;
#pragma unroll 8
      for (int t = 0; t < TT; ++t) {
        const float x = __half2float(sh[t * STG_STRIDE + tid]) + bo;
        u = fmaf(dcy, u, omd * x);
        ob[(size_t)t * OUT] = u;
      }
    }
    // scan reads finish before next tile's ks=1 cp.async (issued after the
    // post-wait __syncthreads) can touch the aliased stage-1 region.
  }
}

}  // namespace li

extern "C" void kernel_launch(void* const* d_in, const int* in_sizes, int n_in,
                              void* d_out, int out_size) {
  const float* X = (const float*)d_in[0];      // [B,T,IN]
  const float* W = (const float*)d_in[1];      // [OUT,IN]
  const float* bias = (const float*)d_in[2];   // [OUT]
  const float* decay = (const float*)d_in[3];  // [OUT]
  float* out = (float*)d_out;                  // [B,T,OUT]

  static bool init = false;
  if (!init) {
    cudaFuncSetAttribute(li::li_kernel,
                         cudaFuncAttributeMaxDynamicSharedMemorySize,
                         li::SMEM_DYN);
    init = true;
  }
  li::li_kernel<<<li::B * (li::OUT / li::TO), 128, li::SMEM_DYN>>>(
      X, (const float4*)W, bias, decay, out);
}

// round 9
// speedup vs baseline: 2.3302x; 2.3302x over previous
#include <cuda_runtime.h>
#include <cuda_fp16.h>
#include <cstdint>
#include <cstddef>

#define DEVI static __device__ __forceinline__

namespace li {

constexpr int B = 32, T = 1024, IN = 1024, OUT = 1024;
constexpr int TT = 128;                 // time rows per tile (GEMM M)
constexpr int TO = 128;                 // out cols per CTA   (GEMM N)
constexpr int BKH = 64;                 // halves per K slab (= one 128B row)
constexpr int SLABS = IN / BKH;         // 16
constexpr int TILES = T / TT;           // 8
constexpr int G = TILES * SLABS;        // 128 slabs per CTA

constexpr int STAGE_BYTES = (TT + TO) * 128;   // 32 KB (X 16K + W 16K, fp16)
constexpr int STG_STRIDE = 136;                // halves; conflict-free
constexpr int STAGING_OFF = 2 * STAGE_BYTES;   // 65536
constexpr int SMEM_DYN = STAGING_OFF + TT * STG_STRIDE * 2;  // 100352

__device__ __align__(16) __half g_Xh[(size_t)B * T * IN];   // 64MB scratch
__device__ __align__(16) __half g_Wh[(size_t)OUT * IN];     // 2MB scratch

DEVI uint32_t s2u(const void* p) {
  uint32_t a;
  asm("{ .reg .u64 t; cvta.to.shared.u64 t, %1; cvt.u32.u64 %0, t; }"
      : "=r"(a) : "l"(p));
  return a;
}
DEVI void cp16(uint32_t s, const void* g) {
  asm volatile("cp.async.cg.shared.global [%0], [%1], 16;" :: "r"(s), "l"(g)
               : "memory");
}
DEVI void cp_commit() { asm volatile("cp.async.commit_group;" ::: "memory"); }
DEVI void cp_wait0() { asm volatile("cp.async.wait_group 0;" ::: "memory"); }

DEVI void ldsm4(uint32_t* r, uint32_t a) {
  asm volatile("ldmatrix.sync.aligned.m8n8.x4.shared.b16 {%0,%1,%2,%3}, [%4];"
               : "=r"(r[0]), "=r"(r[1]), "=r"(r[2]), "=r"(r[3]) : "r"(a));
}
DEVI void mma16(float* c, const uint32_t* a, const uint32_t* b) {
  asm volatile(
      "mma.sync.aligned.m16n8k16.row.col.f32.f16.f16.f32 "
      "{%0,%1,%2,%3}, {%4,%5,%6,%7}, {%8,%9}, {%0,%1,%2,%3};"
      : "+f"(c[0]), "+f"(c[1]), "+f"(c[2]), "+f"(c[3])
      : "r"(a[0]), "r"(a[1]), "r"(a[2]), "r"(a[3]), "r"(b[0]), "r"(b[1]));
}
DEVI uint32_t packh2(float lo, float hi) {
  uint32_t d;
  asm("cvt.rn.f16x2.f32 %0, %1, %2;" : "=r"(d) : "f"(hi), "f"(lo));
  return d;
}

// ---------------- pre-pass: fp32 -> fp16 conversion into scratch -------------
__global__ void __launch_bounds__(256) cvt_kernel(const float4* __restrict__ X,
                                                  const float4* __restrict__ W) {
  const int64_t nx = (int64_t)B * T * IN / 4;
  const int64_t nw = (int64_t)OUT * IN / 4;
  uint2* xo = reinterpret_cast<uint2*>(g_Xh);
  uint2* wo = reinterpret_cast<uint2*>(g_Wh);
  const int64_t stride = (int64_t)gridDim.x * blockDim.x;
  for (int64_t i = (int64_t)blockIdx.x * blockDim.x + threadIdx.x; i < nx;
       i += stride) {
    float4 v = X[i];
    __half2 a = __float22half2_rn({v.x, v.y});
    __half2 b = __float22half2_rn({v.z, v.w});
    uint2 u;
    u.x = *reinterpret_cast<unsigned*>(&a);
    u.y = *reinterpret_cast<unsigned*>(&b);
    xo[i] = u;
  }
  for (int64_t i = (int64_t)blockIdx.x * blockDim.x + threadIdx.x; i < nw;
       i += stride) {
    float4 v = W[i];
    __half2 a = __float22half2_rn({v.x, v.y});
    __half2 b = __float22half2_rn({v.z, v.w});
    uint2 u;
    u.x = *reinterpret_cast<unsigned*>(&a);
    u.y = *reinterpret_cast<unsigned*>(&b);
    wo[i] = u;
  }
}

// ---------------- main fused GEMM + leaky-integrator scan --------------------
// 128 threads, 4 warps in 2x2 grid, warp tile 64x64, kc-pipelined fragments.
__global__ void __launch_bounds__(128, 2)
li_kernel(const float* __restrict__ bias, const float* __restrict__ decay,
          float* __restrict__ out) {
  extern __shared__ __align__(16) char dsm[];
  const uint32_t sbase = s2u(dsm);

  const int tid = threadIdx.x;
  const int wid = tid >> 5;
  const int lane = tid & 31;
  const int bb = blockIdx.x >> 3;
  const int o0 = (blockIdx.x & 7) * TO;

  // ---- scan state: every thread owns one o-channel ----
  const float dcy = decay[o0 + tid];
  const float omd = 1.0f - dcy;
  const float bo = bias[o0 + tid];
  float u = 0.f;

  // ---- cp.async constants: 16 chunks of 16B per thread ----
  const int lr = tid >> 3;
  const int lc = tid & 7;
  const uint32_t sw_off = (uint32_t)lr * 128 + (uint32_t)((lc ^ (lr & 7)) << 4);
  const __half* Wg = g_Wh + (size_t)(o0 + lr) * IN + lc * 8;
  const __half* Xg0 = g_Xh + ((size_t)bb * T + lr) * IN + lc * 8;

  // ---- mma per-thread constants ----
  const int warp_m = wid >> 1, warp_n = wid & 1;
  const int r = lane & 7;
  const int khA = lane >> 4;
  const int khB = (lane >> 3) & 1;
  const uint32_t aBase =
      (uint32_t)(warp_m * 64 + ((lane >> 3) & 1) * 8 + r) * 128;
  const uint32_t bBase =
      (uint32_t)(TT * 128) +
      (uint32_t)(warp_n * 64 + ((lane >> 4) << 3) + r) * 128;

  float acc[4][8][4];

  auto load_slab = [&](int g) {
    const int t0 = (g >> 4) * TT;
    const int k0 = (g & 15) * BKH;
    const uint32_t sb = sbase + (uint32_t)(g & 1) * STAGE_BYTES;
    const __half* Xg = Xg0 + (size_t)t0 * IN + k0;
    const __half* Ws = Wg + k0;
#pragma unroll
    for (int i = 0; i < 8; ++i)
      cp16(sb + sw_off + (uint32_t)i * 2048, Xg + (size_t)i * 16 * IN);
#pragma unroll
    for (int i = 0; i < 8; ++i)
      cp16(sb + (uint32_t)(TT * 128) + sw_off + (uint32_t)i * 2048,
           Ws + (size_t)i * 16 * IN);
  };

  int g = 0;
  load_slab(0);
  cp_commit();

  for (int tile = 0; tile < TILES; ++tile) {
#pragma unroll
    for (int mf = 0; mf < 4; ++mf)
#pragma unroll
      for (int nf = 0; nf < 8; ++nf)
#pragma unroll
        for (int j = 0; j < 4; ++j) acc[mf][nf][j] = 0.f;

    for (int ks = 0; ks < SLABS; ++ks) {
      cp_wait0();
      __syncthreads();
      const uint32_t sb = sbase + (uint32_t)(g & 1) * STAGE_BYTES;

      // ---- kc-pipelined fragment loads + MMAs ----
      uint32_t A[2][4][4], Bf[2][4][4];
      // preload kc=0 fragments first (before the cp.async issue burst)
      {
        const uint32_t swA = (uint32_t)((khA ^ r) << 4);
        const uint32_t swB = (uint32_t)((khB ^ r) << 4);
#pragma unroll
        for (int mf = 0; mf < 4; ++mf)
          ldsm4(A[0][mf], sb + aBase + (uint32_t)mf * 2048 + swA);
#pragma unroll
        for (int p = 0; p < 4; ++p)
          ldsm4(Bf[0][p], sb + bBase + (uint32_t)p * 2048 + swB);
      }
      // issue next slab's loads while kc=0 fragments are in flight
      if (g + 1 < G) {
        load_slab(g + 1);
        cp_commit();
      }
#pragma unroll
      for (int kc = 0; kc < 4; ++kc) {
        const int pb = kc & 1;
        if (kc < 3) {  // prefetch next phase's fragments
          const uint32_t swA = (uint32_t)(((2 * (kc + 1) + khA) ^ r) << 4);
          const uint32_t swB = (uint32_t)(((2 * (kc + 1) + khB) ^ r) << 4);
#pragma unroll
          for (int mf = 0; mf < 4; ++mf)
            ldsm4(A[pb ^ 1][mf], sb + aBase + (uint32_t)mf * 2048 + swA);
#pragma unroll
          for (int p = 0; p < 4; ++p)
            ldsm4(Bf[pb ^ 1][p], sb + bBase + (uint32_t)p * 2048 + swB);
        }
#pragma unroll
        for (int mf = 0; mf < 4; ++mf)
#pragma unroll
          for (int nf = 0; nf < 8; ++nf)
            mma16(acc[mf][nf], A[pb][mf], &Bf[pb][nf >> 1][(nf & 1) * 2]);
      }
      ++g;
    }

    // ---- epilogue: fragments -> fp16 staging [t][o] ----
    unsigned* stg_u = reinterpret_cast<unsigned*>(dsm + STAGING_OFF);
#pragma unroll
    for (int mf = 0; mf < 4; ++mf)
#pragma unroll
      for (int nf = 0; nf < 8; ++nf) {
        const int row = warp_m * 64 + mf * 16 + (lane >> 2);
        const int col = warp_n * 64 + nf * 8 + 2 * (lane & 3);
        stg_u[(row * STG_STRIDE + col) >> 1] =
            packh2(acc[mf][nf][0], acc[mf][nf][1]);
        stg_u[((row + 8) * STG_STRIDE + col) >> 1] =
            packh2(acc[mf][nf][2], acc[mf][nf][3]);
      }
    __syncthreads();

    // ---- fused leaky-integrator scan; carry u persists across tiles ----
    {
      const __half* sh = reinterpret_cast<const __half*>(dsm + STAGING_OFF);
      float* ob = out + ((size_t)bb * T + tile * TT) * OUT + o0 + tid;
#pragma unroll 8
      for (int t = 0; t < TT; ++t) {
        const float x = __half2float(sh[t * STG_STRIDE + tid]) + bo;
        u = fmaf(dcy, u, omd * x);
        ob[(size_t)t * OUT] = u;
      }
    }
  }
}

}  // namespace li

extern "C" void kernel_launch(void* const* d_in, const int* in_sizes, int n_in,
                              void* d_out, int out_size) {
  const float* X = (const float*)d_in[0];      // [B,T,IN]
  const float* W = (const float*)d_in[1];      // [OUT,IN]
  const float* bias = (const float*)d_in[2];   // [OUT]
  const float* decay = (const float*)d_in[3];  // [OUT]
  float* out = (float*)d_out;                  // [B,T,OUT]

  static bool init = false;
  if (!init) {
    cudaFuncSetAttribute(li::li_kernel,
                         cudaFuncAttributeMaxDynamicSharedMemorySize,
                         li::SMEM_DYN);
    init = true;
  }
  li::cvt_kernel<<<1184, 256>>>((const float4*)X, (const float4*)W);
  li::li_kernel<<<li::B * (li::OUT / li::TO), 128, li::SMEM_DYN>>>(bias, decay,
                                                                   out);
}